// round 5
// baseline (speedup 1.0000x reference)
#include <cuda_runtime.h>
#include <cstdint>

#define NAG   4096
#define TOPK  12
#define NSEL  13                 // extract 13, fix up ordering with real sqrt
#define NITEMS (NAG * TOPK)      // 49152
#define T1    256                // threads, topk kernel
#define EPT   16                 // elements per thread = 4096/256
#define NW    (T1 / 32)          // 8 warps
#define NCAND (NW * NSEL)        // 104 stage-2 candidates

// fused MLP tiling
#define TILE_I 64                // items per block
#define HSTR   68                // padded row stride (floats)
#define SMEM_FLOATS ((64 + 128) * HSTR)
#define SMEM_BYTES  (SMEM_FLOATS * 4)   // 52,224 B dynamic

#define U64MAX 0xFFFFFFFFFFFFFFFFULL

__device__ int   g_topk_idx[NITEMS];
__device__ float g_W2t[64 * 128];        // [k][m]
__device__ float g_W3t[128 * 64];        // [k][o]

static __device__ __forceinline__ unsigned long long
u64min(unsigned long long a, unsigned long long b) { return (b < a) ? b : a; }

// ---------------------------------------------------------------------------
// Kernel 1: per-row top-12 via lazy selection (no per-thread sort).
// Keys: (s_bits << 32) | j, s = (x0^2+1e-6)+(x1^2+1e-6) -- sqrt-free, keys
// unique (low bits j). Stage 1: per-warp 13x shuffle-argmin with mask-based
// lazy recompute (all register indices static). Stage 2: warp 0 merges the
// 104 candidates. Fixup: re-key the 13 by (sqrt_bits, j), insertion sort,
// keep 12 -- exact reference semantics (sqrt_rn is monotone).
// ---------------------------------------------------------------------------
__global__ void __launch_bounds__(T1) topk_kernel(const float* __restrict__ x) {
    const int i    = blockIdx.x;
    const int tid  = threadIdx.x;
    const int w    = tid >> 5;
    const int lane = tid & 31;
    const float* row = x + (size_t)i * (NAG * 4);

    unsigned long long keys[EPT];
#pragma unroll
    for (int t = 0; t < EPT; ++t) {
        const int j = tid + t * T1;
        const float2 v = *reinterpret_cast<const float2*>(row + (size_t)j * 4);
        const float s = __fadd_rn(__fadd_rn(__fmul_rn(v.x, v.x), 1e-6f),
                                  __fadd_rn(__fmul_rn(v.y, v.y), 1e-6f));
        keys[t] = ((unsigned long long)__float_as_uint(s) << 32) | (unsigned)j;
    }

    // per-thread running minimum over unused keys
    unsigned long long mymin = keys[0];
#pragma unroll
    for (int t = 1; t < EPT; ++t) mymin = u64min(mymin, keys[t]);
    unsigned used = 0;

    __shared__ unsigned long long warp13[NW * NSEL];

    // stage 1: per-warp top-13, barrier-free
#pragma unroll 1
    for (int pass = 0; pass < NSEL; ++pass) {
        unsigned long long v = mymin;
#pragma unroll
        for (int off = 16; off > 0; off >>= 1) {
            const unsigned long long o = __shfl_xor_sync(0xffffffffu, v, off);
            v = u64min(v, o);
        }
        if (mymin == v) {               // unique winner in this warp
#pragma unroll
            for (int t = 0; t < EPT; ++t)
                if (keys[t] == v) used |= (1u << t);
            unsigned long long m = U64MAX;
#pragma unroll
            for (int t = 0; t < EPT; ++t)
                if (!((used >> t) & 1u)) m = u64min(m, keys[t]);
            mymin = m;
        }
        if (lane == 0) warp13[w * NSEL + pass] = v;
    }
    __syncthreads();

    // stage 2: warp 0 merges 104 candidates (4 per lane, padded)
    if (w == 0) {
        unsigned long long c0 = warp13[lane];
        unsigned long long c1 = warp13[lane + 32];
        unsigned long long c2 = warp13[lane + 64];
        unsigned long long c3 = (lane + 96 < NCAND) ? warp13[lane + 96] : U64MAX;

        unsigned long long fk[NSEL];
#pragma unroll
        for (int pass = 0; pass < NSEL; ++pass) {
            unsigned long long m = u64min(u64min(c0, c1), u64min(c2, c3));
            unsigned long long v = m;
#pragma unroll
            for (int off = 16; off > 0; off >>= 1) {
                const unsigned long long o = __shfl_xor_sync(0xffffffffu, v, off);
                v = u64min(v, o);
            }
            if (c0 == v)      c0 = U64MAX;
            else if (c1 == v) c1 = U64MAX;
            else if (c2 == v) c2 = U64MAX;
            else if (c3 == v) c3 = U64MAX;
            fk[pass] = v;
        }

        // fixup on lane 0: re-key by (sqrt_bits, j), insertion sort, keep 12
        if (lane == 0) {
#pragma unroll
            for (int t = 0; t < NSEL; ++t) {
                const unsigned long long k = fk[t];
                const float s  = __uint_as_float((unsigned)(k >> 32));
                const float dn = __fsqrt_rn(s);
                fk[t] = ((unsigned long long)__float_as_uint(dn) << 32)
                      | (k & 0xFFFFFFFFULL);
            }
#pragma unroll
            for (int a = 1; a < NSEL; ++a) {
                const unsigned long long key = fk[a];
                int b = a - 1;
#pragma unroll
                for (int q = 0; q < NSEL - 1; ++q) {
                    if (b >= 0 && fk[b] > key) { fk[b + 1] = fk[b]; b--; }
                }
                fk[b + 1] = key;
            }
#pragma unroll
            for (int t = 0; t < TOPK; ++t)
                g_topk_idx[i * TOPK + t] = (int)(unsigned)(fk[t] & 0xFFFFFFFFULL);
        }
    }
}

// ---------------------------------------------------------------------------
// Kernel T: transpose W2 [128m][64k] -> W2t [64k][128m],
//           W3 [64o][128m] -> W3t [128m][64o]
// ---------------------------------------------------------------------------
__global__ void __launch_bounds__(256) transpose_kernel(
    const float* __restrict__ W2, const float* __restrict__ W3)
{
    const int tid = threadIdx.x;
    for (int s = tid; s < 128 * 64; s += 256) {
        const int m = s >> 6, k = s & 63;
        g_W2t[k * 128 + m] = W2[s];
    }
    for (int s = tid; s < 64 * 128; s += 256) {
        const int o = s >> 7, m = s & 127;
        g_W3t[m * 64 + o] = W3[s];
    }
}

// ---------------------------------------------------------------------------
// Fused MLP kernel (unchanged from round 4): per block = 64 items.
// ---------------------------------------------------------------------------
__global__ void __launch_bounds__(256, 3) fused_mlp_kernel(
    const float* __restrict__ x,  const float* __restrict__ rp,
    const float* __restrict__ W1, const float* __restrict__ b1,
    const float* __restrict__ b2, const float* __restrict__ b3,
    const float* __restrict__ W4, const float* __restrict__ b4,
    float* __restrict__ out)
{
    extern __shared__ float smem[];
    float* H1s = smem;                   // [64][HSTR]
    float* H2s = smem + 64 * HSTR;       // [128][HSTR]
    float* red = smem;                   // reuse H1s area after stage B

    __shared__ float W1s[64 * 6];
    __shared__ float b1s[64];
    __shared__ float masks[TILE_I];

    const int tid = threadIdx.x;
    for (int s = tid; s < 384; s += 256) W1s[s] = W1[s];
    if (tid < 64) b1s[tid] = b1[tid];
    __syncthreads();

    // ---------------- stage A: features + layer1 (6 -> 64) ----------------
    {
        const int iloc = tid & 63;
        const int q    = tid >> 6;           // 4 threads per item
        const int item = blockIdx.x * TILE_I + iloc;
        const int i = item / TOPK;
        const int j = g_topk_idx[item];

        const float4 v = *reinterpret_cast<const float4*>(
            x + ((size_t)i * NAG + (size_t)j) * 4);
        const float s2 = __fadd_rn(__fadd_rn(__fmul_rn(v.x, v.x), 1e-4f),
                                   __fadd_rn(__fmul_rn(v.y, v.y), 1e-4f));
        const float dn = __fsqrt_rn(s2);
        const float r  = rp[0];
        const float mk = (dn <= 1.0f) ? 1.0f : 0.0f;
        const float f0 = v.x, f1 = v.y, f2 = v.z, f3 = v.w;
        const float f4 = (i == j) ? 1.0f : 0.0f;
        const float f5 = dn - r;

        const int o0 = q * 16;
#pragma unroll
        for (int oo = 0; oo < 16; ++oo) {
            const int o = o0 + oo;
            const float* wp = W1s + o * 6;
            float a = b1s[o];
            a = fmaf(wp[0], f0, a); a = fmaf(wp[1], f1, a); a = fmaf(wp[2], f2, a);
            a = fmaf(wp[3], f3, a); a = fmaf(wp[4], f4, a); a = fmaf(wp[5], f5, a);
            H1s[o * HSTR + iloc] = fmaxf(a, 0.0f);
        }

        if (q == 0) {
            masks[iloc] = mk;
            out[NITEMS + item] = mk;
            out[2 * NITEMS + 2 * item + 0] = (float)i;
            out[2 * NITEMS + 2 * item + 1] = (float)j;
        }
    }
    __syncthreads();

    // ------------- stage B: layer2 GEMM (K=64), 4m x 8i tiles --------------
    {
        const int tm = tid >> 3;             // 0..31
        const int ti = tid & 7;              // 0..7
        const int m0 = tm * 4;
        const int i0 = ti * 8;

        float acc[4][8];
#pragma unroll
        for (int mm = 0; mm < 4; ++mm) {
            const float b = b2[m0 + mm];
#pragma unroll
            for (int ii = 0; ii < 8; ++ii) acc[mm][ii] = b;
        }

#pragma unroll 4
        for (int k = 0; k < 64; ++k) {
            const float4 a0 = *reinterpret_cast<const float4*>(g_W2t + k * 128 + m0);
            const float4 x0 = *reinterpret_cast<const float4*>(H1s + k * HSTR + i0);
            const float4 x1 = *reinterpret_cast<const float4*>(H1s + k * HSTR + i0 + 4);
            const float av[4] = {a0.x, a0.y, a0.z, a0.w};
            const float xv[8] = {x0.x, x0.y, x0.z, x0.w, x1.x, x1.y, x1.z, x1.w};
#pragma unroll
            for (int mm = 0; mm < 4; ++mm)
#pragma unroll
                for (int ii = 0; ii < 8; ++ii)
                    acc[mm][ii] = fmaf(av[mm], xv[ii], acc[mm][ii]);
        }

#pragma unroll
        for (int mm = 0; mm < 4; ++mm) {
            float* dst = H2s + (m0 + mm) * HSTR + i0;
            float4 s0, s1;
            s0.x = fmaxf(acc[mm][0], 0.f); s0.y = fmaxf(acc[mm][1], 0.f);
            s0.z = fmaxf(acc[mm][2], 0.f); s0.w = fmaxf(acc[mm][3], 0.f);
            s1.x = fmaxf(acc[mm][4], 0.f); s1.y = fmaxf(acc[mm][5], 0.f);
            s1.z = fmaxf(acc[mm][6], 0.f); s1.w = fmaxf(acc[mm][7], 0.f);
            *reinterpret_cast<float4*>(dst)     = s0;
            *reinterpret_cast<float4*>(dst + 4) = s1;
        }
    }
    __syncthreads();

    // ------- stage C: layer3 GEMM (K=128), 4o x 4i tiles + layer4 ----------
    {
        const int to = tid >> 4;             // 0..15
        const int ti = tid & 15;             // 0..15
        const int o0 = to * 4;
        const int i0 = ti * 4;

        float acc[4][4];
#pragma unroll
        for (int mm = 0; mm < 4; ++mm) {
            const float b = b3[o0 + mm];
#pragma unroll
            for (int ii = 0; ii < 4; ++ii) acc[mm][ii] = b;
        }

#pragma unroll 4
        for (int k = 0; k < 128; ++k) {
            const float4 a0 = *reinterpret_cast<const float4*>(g_W3t + k * 64 + o0);
            const float4 x0 = *reinterpret_cast<const float4*>(H2s + k * HSTR + i0);
            const float av[4] = {a0.x, a0.y, a0.z, a0.w};
            const float xv[4] = {x0.x, x0.y, x0.z, x0.w};
#pragma unroll
            for (int mm = 0; mm < 4; ++mm)
#pragma unroll
                for (int ii = 0; ii < 4; ++ii)
                    acc[mm][ii] = fmaf(av[mm], xv[ii], acc[mm][ii]);
        }

        // partial layer4 dot over this thread's 4 o's (into reused H1s area)
        float w4v[4];
#pragma unroll
        for (int mm = 0; mm < 4; ++mm) w4v[mm] = W4[o0 + mm];

#pragma unroll
        for (int ii = 0; ii < 4; ++ii) {
            float p = 0.f;
#pragma unroll
            for (int mm = 0; mm < 4; ++mm)
                p = fmaf(w4v[mm], fmaxf(acc[mm][ii], 0.f), p);
            red[to * HSTR + i0 + ii] = p;
        }
    }
    __syncthreads();

    // final: one thread per item sums 16 partials
    if (tid < TILE_I) {
        const int item = blockIdx.x * TILE_I + tid;
        float s = red[tid];
#pragma unroll
        for (int g = 1; g < 16; ++g) s += red[g * HSTR + tid];
        out[item] = (s + b4[0]) * masks[tid];
    }
}

extern "C" void kernel_launch(void* const* d_in, const int* in_sizes, int n_in,
                              void* d_out, int out_size) {
    const float* x  = (const float*)d_in[0];
    const float* r  = (const float*)d_in[1];
    const float* W1 = (const float*)d_in[2];
    const float* b1 = (const float*)d_in[3];
    const float* W2 = (const float*)d_in[4];
    const float* b2 = (const float*)d_in[5];
    const float* W3 = (const float*)d_in[6];
    const float* b3 = (const float*)d_in[7];
    const float* W4 = (const float*)d_in[8];
    const float* b4 = (const float*)d_in[9];
    float* out = (float*)d_out;

    cudaFuncSetAttribute(fused_mlp_kernel,
                         cudaFuncAttributeMaxDynamicSharedMemorySize, SMEM_BYTES);

    topk_kernel<<<NAG, T1>>>(x);
    transpose_kernel<<<1, 256>>>(W2, W3);
    fused_mlp_kernel<<<NITEMS / TILE_I, 256, SMEM_BYTES>>>(
        x, r, W1, b1, b2, b3, W4, b4, out);
}

// round 6
// speedup vs baseline: 1.1622x; 1.1622x over previous
#include <cuda_runtime.h>
#include <cstdint>

#define NAG   4096
#define TOPK  12
#define NSEL  13                 // extract 13, fix up ordering with real sqrt
#define NITEMS (NAG * TOPK)      // 49152
#define T1    256                // threads, topk kernel
#define EPT   16                 // elements per thread = 4096/256

// fused MLP tiling
#define TILE_I 64                // items per block
#define HSTR   68                // padded row stride (floats)
#define SMEM_FLOATS ((64 + 128) * HSTR)
#define SMEM_BYTES  (SMEM_FLOATS * 4)   // 52,224 B dynamic

#define U64MAX 0xFFFFFFFFFFFFFFFFULL

__device__ int   g_topk_idx[NITEMS];
__device__ float g_W2t[64 * 128];        // [k][m]
__device__ float g_W3t[128 * 64];        // [k][o]

static __device__ __forceinline__ unsigned long long
u64min(unsigned long long a, unsigned long long b) { return (b < a) ? b : a; }

// ---------------------------------------------------------------------------
// Kernel 1: per-row top-12 via deterministic threshold filtering.
//  s = (x0^2+1e-6)+(x1^2+1e-6) > 0, so u32 bit order == float order.
//  t = max over 13 disjoint groups of per-thread minima  =>  count(s<=t) >= 13
//  (each group min is an actual element). Candidates (s<=t) pushed as exact
//  u64 (s_bits<<32|j) keys into a worst-case-sized smem buffer; warp 0 does
//  13 exact extract-min passes, then re-keys by (sqrt_bits,j) and keeps 12
//  (sqrt_rn monotone => exact reference semantics incl. rounding-collision
//  tie-breaks).
// ---------------------------------------------------------------------------
__global__ void __launch_bounds__(T1) topk_kernel(const float* __restrict__ x) {
    const int i    = blockIdx.x;
    const int tid  = threadIdx.x;
    const int w    = tid >> 5;
    const int lane = tid & 31;
    const float* row = x + (size_t)i * (NAG * 4);

    unsigned sb[EPT];
#pragma unroll
    for (int t = 0; t < EPT; ++t) {
        const int j = tid + t * T1;
        const float2 v = *reinterpret_cast<const float2*>(row + (size_t)j * 4);
        const float s = __fadd_rn(__fadd_rn(__fmul_rn(v.x, v.x), 1e-6f),
                                  __fadd_rn(__fmul_rn(v.y, v.y), 1e-6f));
        sb[t] = __float_as_uint(s);
    }

    unsigned mymin = sb[0];
#pragma unroll
    for (int t = 1; t < EPT; ++t) mymin = (sb[t] < mymin) ? sb[t] : mymin;

    __shared__ unsigned tmin[T1];
    __shared__ unsigned sthresh;
    __shared__ int      scnt;
    __shared__ unsigned long long buf[NAG];     // worst-case capacity: safe

    tmin[tid] = mymin;
    if (tid == 0) scnt = 0;
    __syncthreads();

    // threshold: max of 13 group minima (12 groups of 20 + 1 group of 16)
    if (w == 0 && lane < 13) {
        const int start = lane * 20;
        const int len   = (lane == 12) ? 16 : 20;
        unsigned g = tmin[start];
        for (int q = 1; q < len; ++q) {
            const unsigned v = tmin[start + q];
            g = (v < g) ? v : g;
        }
        const unsigned mx = __reduce_max_sync(0x1FFFu, g);
        if (lane == 0) sthresh = mx;
    }
    __syncthreads();

    const unsigned thr = sthresh;
#pragma unroll
    for (int t = 0; t < EPT; ++t) {
        if (sb[t] <= thr) {
            const int pos = atomicAdd(&scnt, 1);
            buf[pos] = ((unsigned long long)sb[t] << 32)
                     | (unsigned)(tid + t * T1);
        }
    }
    __syncthreads();

    // warp 0: 13 exact extract-min passes over the candidate buffer
    if (w == 0) {
        const int n = scnt;                      // n >= 13 guaranteed
        unsigned long long fk[NSEL];
#pragma unroll
        for (int pass = 0; pass < NSEL; ++pass) {
            unsigned long long lmin = U64MAX;
            for (int idx = lane; idx < n; idx += 32)
                lmin = u64min(lmin, buf[idx]);
            unsigned long long v = lmin;
#pragma unroll
            for (int off = 16; off > 0; off >>= 1) {
                const unsigned long long o = __shfl_xor_sync(0xffffffffu, v, off);
                v = u64min(v, o);
            }
            if (lmin == v && v != U64MAX) {      // unique winner lane
                for (int idx = lane; idx < n; idx += 32)
                    if (buf[idx] == v) buf[idx] = U64MAX;
            }
            fk[pass] = v;
        }

        // fixup on lane 0: re-key by (sqrt_bits, j), insertion sort, keep 12
        if (lane == 0) {
#pragma unroll
            for (int t = 0; t < NSEL; ++t) {
                const unsigned long long k = fk[t];
                const float s  = __uint_as_float((unsigned)(k >> 32));
                const float dn = __fsqrt_rn(s);
                fk[t] = ((unsigned long long)__float_as_uint(dn) << 32)
                      | (k & 0xFFFFFFFFULL);
            }
#pragma unroll
            for (int a = 1; a < NSEL; ++a) {
                const unsigned long long key = fk[a];
                int b = a - 1;
#pragma unroll
                for (int q = 0; q < NSEL - 1; ++q) {
                    if (b >= 0 && fk[b] > key) { fk[b + 1] = fk[b]; b--; }
                }
                fk[b + 1] = key;
            }
#pragma unroll
            for (int t = 0; t < TOPK; ++t)
                g_topk_idx[i * TOPK + t] = (int)(unsigned)(fk[t] & 0xFFFFFFFFULL);
        }
    }
}

// ---------------------------------------------------------------------------
// Kernel T: transpose W2 [128m][64k] -> W2t [64k][128m],
//           W3 [64o][128m] -> W3t [128m][64o]
// ---------------------------------------------------------------------------
__global__ void __launch_bounds__(256) transpose_kernel(
    const float* __restrict__ W2, const float* __restrict__ W3)
{
    const int tid = threadIdx.x;
    for (int s = tid; s < 128 * 64; s += 256) {
        const int m = s >> 6, k = s & 63;
        g_W2t[k * 128 + m] = W2[s];
    }
    for (int s = tid; s < 64 * 128; s += 256) {
        const int o = s >> 7, m = s & 127;
        g_W3t[m * 64 + o] = W3[s];
    }
}

// ---------------------------------------------------------------------------
// Fused MLP kernel (unchanged, proven in round 4): per block = 64 items.
// ---------------------------------------------------------------------------
__global__ void __launch_bounds__(256, 3) fused_mlp_kernel(
    const float* __restrict__ x,  const float* __restrict__ rp,
    const float* __restrict__ W1, const float* __restrict__ b1,
    const float* __restrict__ b2, const float* __restrict__ b3,
    const float* __restrict__ W4, const float* __restrict__ b4,
    float* __restrict__ out)
{
    extern __shared__ float smem[];
    float* H1s = smem;                   // [64][HSTR]
    float* H2s = smem + 64 * HSTR;       // [128][HSTR]
    float* red = smem;                   // reuse H1s area after stage B

    __shared__ float W1s[64 * 6];
    __shared__ float b1s[64];
    __shared__ float masks[TILE_I];

    const int tid = threadIdx.x;
    for (int s = tid; s < 384; s += 256) W1s[s] = W1[s];
    if (tid < 64) b1s[tid] = b1[tid];
    __syncthreads();

    // ---------------- stage A: features + layer1 (6 -> 64) ----------------
    {
        const int iloc = tid & 63;
        const int q    = tid >> 6;           // 4 threads per item
        const int item = blockIdx.x * TILE_I + iloc;
        const int i = item / TOPK;
        const int j = g_topk_idx[item];

        const float4 v = *reinterpret_cast<const float4*>(
            x + ((size_t)i * NAG + (size_t)j) * 4);
        const float s2 = __fadd_rn(__fadd_rn(__fmul_rn(v.x, v.x), 1e-4f),
                                   __fadd_rn(__fmul_rn(v.y, v.y), 1e-4f));
        const float dn = __fsqrt_rn(s2);
        const float r  = rp[0];
        const float mk = (dn <= 1.0f) ? 1.0f : 0.0f;
        const float f0 = v.x, f1 = v.y, f2 = v.z, f3 = v.w;
        const float f4 = (i == j) ? 1.0f : 0.0f;
        const float f5 = dn - r;

        const int o0 = q * 16;
#pragma unroll
        for (int oo = 0; oo < 16; ++oo) {
            const int o = o0 + oo;
            const float* wp = W1s + o * 6;
            float a = b1s[o];
            a = fmaf(wp[0], f0, a); a = fmaf(wp[1], f1, a); a = fmaf(wp[2], f2, a);
            a = fmaf(wp[3], f3, a); a = fmaf(wp[4], f4, a); a = fmaf(wp[5], f5, a);
            H1s[o * HSTR + iloc] = fmaxf(a, 0.0f);
        }

        if (q == 0) {
            masks[iloc] = mk;
            out[NITEMS + item] = mk;
            out[2 * NITEMS + 2 * item + 0] = (float)i;
            out[2 * NITEMS + 2 * item + 1] = (float)j;
        }
    }
    __syncthreads();

    // ------------- stage B: layer2 GEMM (K=64), 4m x 8i tiles --------------
    {
        const int tm = tid >> 3;             // 0..31
        const int ti = tid & 7;              // 0..7
        const int m0 = tm * 4;
        const int i0 = ti * 8;

        float acc[4][8];
#pragma unroll
        for (int mm = 0; mm < 4; ++mm) {
            const float b = b2[m0 + mm];
#pragma unroll
            for (int ii = 0; ii < 8; ++ii) acc[mm][ii] = b;
        }

#pragma unroll 4
        for (int k = 0; k < 64; ++k) {
            const float4 a0 = *reinterpret_cast<const float4*>(g_W2t + k * 128 + m0);
            const float4 x0 = *reinterpret_cast<const float4*>(H1s + k * HSTR + i0);
            const float4 x1 = *reinterpret_cast<const float4*>(H1s + k * HSTR + i0 + 4);
            const float av[4] = {a0.x, a0.y, a0.z, a0.w};
            const float xv[8] = {x0.x, x0.y, x0.z, x0.w, x1.x, x1.y, x1.z, x1.w};
#pragma unroll
            for (int mm = 0; mm < 4; ++mm)
#pragma unroll
                for (int ii = 0; ii < 8; ++ii)
                    acc[mm][ii] = fmaf(av[mm], xv[ii], acc[mm][ii]);
        }

#pragma unroll
        for (int mm = 0; mm < 4; ++mm) {
            float* dst = H2s + (m0 + mm) * HSTR + i0;
            float4 s0, s1;
            s0.x = fmaxf(acc[mm][0], 0.f); s0.y = fmaxf(acc[mm][1], 0.f);
            s0.z = fmaxf(acc[mm][2], 0.f); s0.w = fmaxf(acc[mm][3], 0.f);
            s1.x = fmaxf(acc[mm][4], 0.f); s1.y = fmaxf(acc[mm][5], 0.f);
            s1.z = fmaxf(acc[mm][6], 0.f); s1.w = fmaxf(acc[mm][7], 0.f);
            *reinterpret_cast<float4*>(dst)     = s0;
            *reinterpret_cast<float4*>(dst + 4) = s1;
        }
    }
    __syncthreads();

    // ------- stage C: layer3 GEMM (K=128), 4o x 4i tiles + layer4 ----------
    {
        const int to = tid >> 4;             // 0..15
        const int ti = tid & 15;             // 0..15
        const int o0 = to * 4;
        const int i0 = ti * 4;

        float acc[4][4];
#pragma unroll
        for (int mm = 0; mm < 4; ++mm) {
            const float b = b3[o0 + mm];
#pragma unroll
            for (int ii = 0; ii < 4; ++ii) acc[mm][ii] = b;
        }

#pragma unroll 4
        for (int k = 0; k < 128; ++k) {
            const float4 a0 = *reinterpret_cast<const float4*>(g_W3t + k * 64 + o0);
            const float4 x0 = *reinterpret_cast<const float4*>(H2s + k * HSTR + i0);
            const float av[4] = {a0.x, a0.y, a0.z, a0.w};
            const float xv[4] = {x0.x, x0.y, x0.z, x0.w};
#pragma unroll
            for (int mm = 0; mm < 4; ++mm)
#pragma unroll
                for (int ii = 0; ii < 4; ++ii)
                    acc[mm][ii] = fmaf(av[mm], xv[ii], acc[mm][ii]);
        }

        // partial layer4 dot over this thread's 4 o's (into reused H1s area)
        float w4v[4];
#pragma unroll
        for (int mm = 0; mm < 4; ++mm) w4v[mm] = W4[o0 + mm];

#pragma unroll
        for (int ii = 0; ii < 4; ++ii) {
            float p = 0.f;
#pragma unroll
            for (int mm = 0; mm < 4; ++mm)
                p = fmaf(w4v[mm], fmaxf(acc[mm][ii], 0.f), p);
            red[to * HSTR + i0 + ii] = p;
        }
    }
    __syncthreads();

    // final: one thread per item sums 16 partials
    if (tid < TILE_I) {
        const int item = blockIdx.x * TILE_I + tid;
        float s = red[tid];
#pragma unroll
        for (int g = 1; g < 16; ++g) s += red[g * HSTR + tid];
        out[item] = (s + b4[0]) * masks[tid];
    }
}

extern "C" void kernel_launch(void* const* d_in, const int* in_sizes, int n_in,
                              void* d_out, int out_size) {
    const float* x  = (const float*)d_in[0];
    const float* r  = (const float*)d_in[1];
    const float* W1 = (const float*)d_in[2];
    const float* b1 = (const float*)d_in[3];
    const float* W2 = (const float*)d_in[4];
    const float* b2 = (const float*)d_in[5];
    const float* W3 = (const float*)d_in[6];
    const float* b3 = (const float*)d_in[7];
    const float* W4 = (const float*)d_in[8];
    const float* b4 = (const float*)d_in[9];
    float* out = (float*)d_out;

    cudaFuncSetAttribute(fused_mlp_kernel,
                         cudaFuncAttributeMaxDynamicSharedMemorySize, SMEM_BYTES);

    topk_kernel<<<NAG, T1>>>(x);
    transpose_kernel<<<1, 256>>>(W2, W3);
    fused_mlp_kernel<<<NITEMS / TILE_I, 256, SMEM_BYTES>>>(
        x, r, W1, b1, b2, b3, W4, b4, out);
}

// round 7
// speedup vs baseline: 1.5052x; 1.2951x over previous
#include <cuda_runtime.h>
#include <cstdint>

#define NAG   4096
#define TOPK  12
#define NSEL  13                 // extract 13, fix up ordering with real sqrt
#define NITEMS (NAG * TOPK)      // 49152
#define T1    256                // threads, streaming kernel
#define EPT   16                 // elements per thread = 4096/256
#define CCAP  256                // per-row candidate capacity

// fused MLP tiling
#define TILE_I 64                // items per block
#define HSTR   68                // padded row stride (floats)
#define SMEM_FLOATS ((64 + 128) * HSTR)
#define SMEM_BYTES  (SMEM_FLOATS * 4)   // 52,224 B dynamic

#define U64MAX 0xFFFFFFFFFFFFFFFFULL

__device__ int   g_topk_idx[NITEMS];
__device__ float g_W2t[64 * 128];        // [k][m]
__device__ float g_W3t[128 * 64];        // [k][o]
__device__ unsigned long long g_cand[NAG * CCAP];   // 8 MB candidate buffer
__device__ int   g_cnt[NAG];

static __device__ __forceinline__ unsigned long long
u64min(unsigned long long a, unsigned long long b) { return (b < a) ? b : a; }

// ---------------------------------------------------------------------------
// Kernel 1a: pure streaming candidate filter (no serial tail, ~1KB smem).
//  s = (x0^2+1e-6)+(x1^2+1e-6) > 0 -> u32 bit order == float order.
//  thr = max of 13 disjoint group minima => count(s<=thr) >= 13 guaranteed.
//  Candidates (s<=thr) stored as u64 (s_bits<<32|j) in g_cand[row][*] via an
//  smem counter; count written by tid 0 (no global atomics, deterministic).
// ---------------------------------------------------------------------------
__global__ void __launch_bounds__(T1) topk_filter_kernel(const float* __restrict__ x) {
    const int i    = blockIdx.x;
    const int tid  = threadIdx.x;
    const int w    = tid >> 5;
    const int lane = tid & 31;
    const float* row = x + (size_t)i * (NAG * 4);

    unsigned sb[EPT];
#pragma unroll
    for (int t = 0; t < EPT; ++t) {
        const int j = tid + t * T1;
        const float2 v = *reinterpret_cast<const float2*>(row + (size_t)j * 4);
        const float s = __fadd_rn(__fadd_rn(__fmul_rn(v.x, v.x), 1e-6f),
                                  __fadd_rn(__fmul_rn(v.y, v.y), 1e-6f));
        sb[t] = __float_as_uint(s);
    }

    unsigned mymin = sb[0];
#pragma unroll
    for (int t = 1; t < EPT; ++t) mymin = (sb[t] < mymin) ? sb[t] : mymin;

    __shared__ unsigned tmin[T1];
    __shared__ unsigned sthresh;
    __shared__ int      scnt;

    tmin[tid] = mymin;
    if (tid == 0) scnt = 0;
    __syncthreads();

    // threshold: max of 13 group minima (12 groups of 20 + 1 group of 16)
    if (w == 0 && lane < 13) {
        const int start = lane * 20;
        const int len   = (lane == 12) ? 16 : 20;
        unsigned g = tmin[start];
        for (int q = 1; q < len; ++q) {
            const unsigned v = tmin[start + q];
            g = (v < g) ? v : g;
        }
        const unsigned mx = __reduce_max_sync(0x1FFFu, g);
        if (lane == 0) sthresh = mx;
    }
    __syncthreads();

    const unsigned thr = sthresh;
    unsigned long long* cand = g_cand + (size_t)i * CCAP;
#pragma unroll
    for (int t = 0; t < EPT; ++t) {
        if (sb[t] <= thr) {
            const int pos = atomicAdd(&scnt, 1);
            if (pos < CCAP)
                cand[pos] = ((unsigned long long)sb[t] << 32)
                          | (unsigned)(tid + t * T1);
        }
    }
    __syncthreads();
    if (tid == 0) g_cnt[i] = scnt;
}

// ---------------------------------------------------------------------------
// Kernel 1b: one warp per row. Extract the 13 smallest keys as 13 passes of
// "min over keys > prev" (keys unique, so no used-marking). If the candidate
// buffer overflowed (count > CCAP, nondeterministic subset), fall back to a
// direct full-row scan -- deterministic and exact. Then re-key the 13 by
// (sqrt_bits, j) (sqrt_rn monotone), insertion sort, keep 12: exact reference
// semantics including sqrt rounding-collision tie-breaks.
// ---------------------------------------------------------------------------
__global__ void __launch_bounds__(256) topk_extract_kernel(const float* __restrict__ x) {
    const int tid  = threadIdx.x;
    const int lane = tid & 31;
    const int i    = blockIdx.x * 8 + (tid >> 5);
    const int n    = g_cnt[i];

    unsigned long long fk[NSEL];
    unsigned long long prev = 0;      // keys >= 2^32 > 0

    if (n <= CCAP) {
        const unsigned long long* cand = g_cand + (size_t)i * CCAP;
        unsigned long long ck[8];     // CCAP/32 = 8
#pragma unroll
        for (int t = 0; t < 8; ++t) {
            const int idx = lane + t * 32;
            ck[t] = (idx < n) ? cand[idx] : U64MAX;
        }
#pragma unroll 1
        for (int pass = 0; pass < NSEL; ++pass) {
            unsigned long long lmin = U64MAX;
#pragma unroll
            for (int t = 0; t < 8; ++t)
                if (ck[t] > prev) lmin = u64min(lmin, ck[t]);
            unsigned long long v = lmin;
#pragma unroll
            for (int off = 16; off > 0; off >>= 1) {
                const unsigned long long o = __shfl_xor_sync(0xffffffffu, v, off);
                v = u64min(v, o);
            }
            fk[pass] = v;
            prev = v;
        }
    } else {
        // overflow fallback: rescan the row directly (deterministic, rare)
        const float* row = x + (size_t)i * (NAG * 4);
#pragma unroll 1
        for (int pass = 0; pass < NSEL; ++pass) {
            unsigned long long lmin = U64MAX;
            for (int t = 0; t < NAG / 32; ++t) {
                const int j = lane + t * 32;
                const float2 v2 = *reinterpret_cast<const float2*>(row + (size_t)j * 4);
                const float s = __fadd_rn(__fadd_rn(__fmul_rn(v2.x, v2.x), 1e-6f),
                                          __fadd_rn(__fmul_rn(v2.y, v2.y), 1e-6f));
                const unsigned long long k =
                    ((unsigned long long)__float_as_uint(s) << 32) | (unsigned)j;
                if (k > prev) lmin = u64min(lmin, k);
            }
            unsigned long long v = lmin;
#pragma unroll
            for (int off = 16; off > 0; off >>= 1) {
                const unsigned long long o = __shfl_xor_sync(0xffffffffu, v, off);
                v = u64min(v, o);
            }
            fk[pass] = v;
            prev = v;
        }
    }

    // fixup on lane 0: re-key by (sqrt_bits, j), insertion sort, keep 12
    if (lane == 0) {
#pragma unroll
        for (int t = 0; t < NSEL; ++t) {
            const unsigned long long k = fk[t];
            const float s  = __uint_as_float((unsigned)(k >> 32));
            const float dn = __fsqrt_rn(s);
            fk[t] = ((unsigned long long)__float_as_uint(dn) << 32)
                  | (k & 0xFFFFFFFFULL);
        }
#pragma unroll
        for (int a = 1; a < NSEL; ++a) {
            const unsigned long long key = fk[a];
            int b = a - 1;
#pragma unroll
            for (int q = 0; q < NSEL - 1; ++q) {
                if (b >= 0 && fk[b] > key) { fk[b + 1] = fk[b]; b--; }
            }
            fk[b + 1] = key;
        }
#pragma unroll
        for (int t = 0; t < TOPK; ++t)
            g_topk_idx[i * TOPK + t] = (int)(unsigned)(fk[t] & 0xFFFFFFFFULL);
    }
}

// ---------------------------------------------------------------------------
// Kernel T: transpose W2 [128m][64k] -> W2t [64k][128m],
//           W3 [64o][128m] -> W3t [128m][64o]
// ---------------------------------------------------------------------------
__global__ void __launch_bounds__(256) transpose_kernel(
    const float* __restrict__ W2, const float* __restrict__ W3)
{
    const int tid = threadIdx.x;
    for (int s = tid; s < 128 * 64; s += 256) {
        const int m = s >> 6, k = s & 63;
        g_W2t[k * 128 + m] = W2[s];
    }
    for (int s = tid; s < 64 * 128; s += 256) {
        const int o = s >> 7, m = s & 127;
        g_W3t[m * 64 + o] = W3[s];
    }
}

// ---------------------------------------------------------------------------
// Fused MLP kernel (unchanged, proven in round 4): per block = 64 items.
// ---------------------------------------------------------------------------
__global__ void __launch_bounds__(256, 3) fused_mlp_kernel(
    const float* __restrict__ x,  const float* __restrict__ rp,
    const float* __restrict__ W1, const float* __restrict__ b1,
    const float* __restrict__ b2, const float* __restrict__ b3,
    const float* __restrict__ W4, const float* __restrict__ b4,
    float* __restrict__ out)
{
    extern __shared__ float smem[];
    float* H1s = smem;                   // [64][HSTR]
    float* H2s = smem + 64 * HSTR;       // [128][HSTR]
    float* red = smem;                   // reuse H1s area after stage B

    __shared__ float W1s[64 * 6];
    __shared__ float b1s[64];
    __shared__ float masks[TILE_I];

    const int tid = threadIdx.x;
    for (int s = tid; s < 384; s += 256) W1s[s] = W1[s];
    if (tid < 64) b1s[tid] = b1[tid];
    __syncthreads();

    // ---------------- stage A: features + layer1 (6 -> 64) ----------------
    {
        const int iloc = tid & 63;
        const int q    = tid >> 6;           // 4 threads per item
        const int item = blockIdx.x * TILE_I + iloc;
        const int i = item / TOPK;
        const int j = g_topk_idx[item];

        const float4 v = *reinterpret_cast<const float4*>(
            x + ((size_t)i * NAG + (size_t)j) * 4);
        const float s2 = __fadd_rn(__fadd_rn(__fmul_rn(v.x, v.x), 1e-4f),
                                   __fadd_rn(__fmul_rn(v.y, v.y), 1e-4f));
        const float dn = __fsqrt_rn(s2);
        const float r  = rp[0];
        const float mk = (dn <= 1.0f) ? 1.0f : 0.0f;
        const float f0 = v.x, f1 = v.y, f2 = v.z, f3 = v.w;
        const float f4 = (i == j) ? 1.0f : 0.0f;
        const float f5 = dn - r;

        const int o0 = q * 16;
#pragma unroll
        for (int oo = 0; oo < 16; ++oo) {
            const int o = o0 + oo;
            const float* wp = W1s + o * 6;
            float a = b1s[o];
            a = fmaf(wp[0], f0, a); a = fmaf(wp[1], f1, a); a = fmaf(wp[2], f2, a);
            a = fmaf(wp[3], f3, a); a = fmaf(wp[4], f4, a); a = fmaf(wp[5], f5, a);
            H1s[o * HSTR + iloc] = fmaxf(a, 0.0f);
        }

        if (q == 0) {
            masks[iloc] = mk;
            out[NITEMS + item] = mk;
            out[2 * NITEMS + 2 * item + 0] = (float)i;
            out[2 * NITEMS + 2 * item + 1] = (float)j;
        }
    }
    __syncthreads();

    // ------------- stage B: layer2 GEMM (K=64), 4m x 8i tiles --------------
    {
        const int tm = tid >> 3;             // 0..31
        const int ti = tid & 7;              // 0..7
        const int m0 = tm * 4;
        const int i0 = ti * 8;

        float acc[4][8];
#pragma unroll
        for (int mm = 0; mm < 4; ++mm) {
            const float b = b2[m0 + mm];
#pragma unroll
            for (int ii = 0; ii < 8; ++ii) acc[mm][ii] = b;
        }

#pragma unroll 4
        for (int k = 0; k < 64; ++k) {
            const float4 a0 = *reinterpret_cast<const float4*>(g_W2t + k * 128 + m0);
            const float4 x0 = *reinterpret_cast<const float4*>(H1s + k * HSTR + i0);
            const float4 x1 = *reinterpret_cast<const float4*>(H1s + k * HSTR + i0 + 4);
            const float av[4] = {a0.x, a0.y, a0.z, a0.w};
            const float xv[8] = {x0.x, x0.y, x0.z, x0.w, x1.x, x1.y, x1.z, x1.w};
#pragma unroll
            for (int mm = 0; mm < 4; ++mm)
#pragma unroll
                for (int ii = 0; ii < 8; ++ii)
                    acc[mm][ii] = fmaf(av[mm], xv[ii], acc[mm][ii]);
        }

#pragma unroll
        for (int mm = 0; mm < 4; ++mm) {
            float* dst = H2s + (m0 + mm) * HSTR + i0;
            float4 s0, s1;
            s0.x = fmaxf(acc[mm][0], 0.f); s0.y = fmaxf(acc[mm][1], 0.f);
            s0.z = fmaxf(acc[mm][2], 0.f); s0.w = fmaxf(acc[mm][3], 0.f);
            s1.x = fmaxf(acc[mm][4], 0.f); s1.y = fmaxf(acc[mm][5], 0.f);
            s1.z = fmaxf(acc[mm][6], 0.f); s1.w = fmaxf(acc[mm][7], 0.f);
            *reinterpret_cast<float4*>(dst)     = s0;
            *reinterpret_cast<float4*>(dst + 4) = s1;
        }
    }
    __syncthreads();

    // ------- stage C: layer3 GEMM (K=128), 4o x 4i tiles + layer4 ----------
    {
        const int to = tid >> 4;             // 0..15
        const int ti = tid & 15;             // 0..15
        const int o0 = to * 4;
        const int i0 = ti * 4;

        float acc[4][4];
#pragma unroll
        for (int mm = 0; mm < 4; ++mm) {
            const float b = b3[o0 + mm];
#pragma unroll
            for (int ii = 0; ii < 4; ++ii) acc[mm][ii] = b;
        }

#pragma unroll 4
        for (int k = 0; k < 128; ++k) {
            const float4 a0 = *reinterpret_cast<const float4*>(g_W3t + k * 64 + o0);
            const float4 x0 = *reinterpret_cast<const float4*>(H2s + k * HSTR + i0);
            const float av[4] = {a0.x, a0.y, a0.z, a0.w};
            const float xv[4] = {x0.x, x0.y, x0.z, x0.w};
#pragma unroll
            for (int mm = 0; mm < 4; ++mm)
#pragma unroll
                for (int ii = 0; ii < 4; ++ii)
                    acc[mm][ii] = fmaf(av[mm], xv[ii], acc[mm][ii]);
        }

        // partial layer4 dot over this thread's 4 o's (into reused H1s area)
        float w4v[4];
#pragma unroll
        for (int mm = 0; mm < 4; ++mm) w4v[mm] = W4[o0 + mm];

#pragma unroll
        for (int ii = 0; ii < 4; ++ii) {
            float p = 0.f;
#pragma unroll
            for (int mm = 0; mm < 4; ++mm)
                p = fmaf(w4v[mm], fmaxf(acc[mm][ii], 0.f), p);
            red[to * HSTR + i0 + ii] = p;
        }
    }
    __syncthreads();

    // final: one thread per item sums 16 partials
    if (tid < TILE_I) {
        const int item = blockIdx.x * TILE_I + tid;
        float s = red[tid];
#pragma unroll
        for (int g = 1; g < 16; ++g) s += red[g * HSTR + tid];
        out[item] = (s + b4[0]) * masks[tid];
    }
}

extern "C" void kernel_launch(void* const* d_in, const int* in_sizes, int n_in,
                              void* d_out, int out_size) {
    const float* x  = (const float*)d_in[0];
    const float* r  = (const float*)d_in[1];
    const float* W1 = (const float*)d_in[2];
    const float* b1 = (const float*)d_in[3];
    const float* W2 = (const float*)d_in[4];
    const float* b2 = (const float*)d_in[5];
    const float* W3 = (const float*)d_in[6];
    const float* b3 = (const float*)d_in[7];
    const float* W4 = (const float*)d_in[8];
    const float* b4 = (const float*)d_in[9];
    float* out = (float*)d_out;

    cudaFuncSetAttribute(fused_mlp_kernel,
                         cudaFuncAttributeMaxDynamicSharedMemorySize, SMEM_BYTES);

    topk_filter_kernel<<<NAG, T1>>>(x);
    topk_extract_kernel<<<NAG / 8, 256>>>(x);
    transpose_kernel<<<1, 256>>>(W2, W3);
    fused_mlp_kernel<<<NITEMS / TILE_I, 256, SMEM_BYTES>>>(
        x, r, W1, b1, b2, b3, W4, b4, out);
}